// round 9
// baseline (speedup 1.0000x reference)
#include <cuda_runtime.h>
#include <cstdint>

// Problem constants
#define LD      64
#define HWD     4096
#define NROWS   65536
#define KCODES  1024
#define ELEMS   4194304
#define LPAD    136         // padded stride (words) -> conflict-free fragment LDS
#define CAND    32          // max candidates per row (overflow -> exact full scan)
#define TAU     2e-3f       // screening slack; bf16 worst-case error ~8.4e-4

// Scratch (static device allocations only)
__device__ int    g_idx[NROWS];
__device__ float  g_en2[KCODES];
__device__ double g_loss;

// Order-preserving float<->uint key for atomicMin over signed floats
__device__ __forceinline__ unsigned fkey(float x) {
    unsigned u = __float_as_uint(x);
    return (u & 0x80000000u) ? ~u : (u | 0x80000000u);
}
__device__ __forceinline__ float funkey(unsigned k) {
    unsigned u = (k & 0x80000000u) ? (k ^ 0x80000000u) : ~k;
    return __uint_as_float(u);
}

// Pack two fp32 -> bf16x2 (lo = even-k element, hi = odd-k)
__device__ __forceinline__ unsigned pack_bf2(float lo, float hi) {
    unsigned r;
    asm("cvt.rn.bf16x2.f32 %0, %1, %2;" : "=r"(r) : "f"(hi), "f"(lo));
    return r;
}

// Warp-level bf16 MMA, D(16x8,f32) += A(16x16) * B(16x8)
#define MMA_BF16(c0,c1,c2,c3, a0,a1,a2,a3, b0,b1) \
    asm volatile("mma.sync.aligned.m16n8k16.row.col.f32.bf16.bf16.f32 " \
        "{%0,%1,%2,%3}, {%4,%5,%6,%7}, {%8,%9}, {%0,%1,%2,%3};" \
        : "+f"(c0), "+f"(c1), "+f"(c2), "+f"(c3) \
        : "r"(a0), "r"(a1), "r"(a2), "r"(a3), "r"(b0), "r"(b1))

// ---------------------------------------------------------------------------
// K1: exact per-code squared norms (separate mul/add, sequential order —
// matches jnp.sum(emb*emb, axis=1) bit-exactly). Zeroes loss accumulator.
// ---------------------------------------------------------------------------
__global__ void en2_kernel(const float* __restrict__ emb) {
    int k = blockIdx.x * blockDim.x + threadIdx.x;
    if (k == 0) g_loss = 0.0;
    if (k < KCODES) {
        const float* e = emb + k * LD;
        float s = 0.0f;
#pragma unroll
        for (int l = 0; l < LD; l++)
            s = __fadd_rn(s, __fmul_rn(e[l], e[l]));
        g_en2[k] = s;
    }
}

// ---------------------------------------------------------------------------
// K2: bf16 tensor-core screen + bit-exact fp32 recheck.
//   Block = 128 rows, 8 warps in 4x2 (M x N): warp tile 32 rows x 64 codes.
//   ns processed in 2 groups of 4 -> acc live set 32 regs (no spills).
//   Screen selects {k : s~_k <= runningmin~ + TAU} (provably contains argmin);
//   exact phase replays reference fp32 arithmetic to decide.
// ---------------------------------------------------------------------------
__global__ void __launch_bounds__(256, 2)
screen_kernel(const float* __restrict__ ze, const float* __restrict__ emb,
              float* __restrict__ out_idx) {
    extern __shared__ unsigned char smem_raw[];
    float*    szf     = (float*)smem_raw;                // [64][LPAD] fp32 zf
    unsigned* szb     = (unsigned*)(szf + 64 * LPAD);    // [32][LPAD] bf16x2 zf pairs
    unsigned* scb     = szb + 32 * LPAD;                 // [32][LPAD] bf16x2 code pairs
    float*    sen2t   = (float*)(scb + 32 * LPAD);       // [128] exact ||e||^2 tile
    unsigned* sminkey = (unsigned*)(sen2t + 128);        // [128] per-row min key
    int*      ccnt    = (int*)(sminkey + 128);           // [128]
    int*      cand    = ccnt + 128;                      // [128][CAND]

    const int tid  = threadIdx.x;
    const int lane = tid & 31, wid = tid >> 5;
    const int rowbase = blockIdx.x * 128;
    const int b   = rowbase >> 12;                   // all 128 rows share b
    const int hw0 = rowbase & 4095;

    if (tid < 128) { sminkey[tid] = 0xFFFFFFFFu; ccnt[tid] = 0; }

    // Load zf tile: fp32 into szf[l][r] AND packed bf16x2 k-pairs into szb.
    for (int i = tid; i < 32 * 128; i += 256) {
        int l2 = i >> 7, r = i & 127;
        float f0 = ze[((size_t)(b * LD + 2 * l2    ) << 12) + hw0 + r];
        float f1 = ze[((size_t)(b * LD + 2 * l2 + 1) << 12) + hw0 + r];
        szf[(2 * l2    ) * LPAD + r] = f0;
        szf[(2 * l2 + 1) * LPAD + r] = f1;
        szb[l2 * LPAD + r] = pack_bf2(f0, f1);
    }
    __syncthreads();

    // Warp tiling
    const int mb = (wid >> 1) << 5;    // row base (0/32/64/96)
    const int nh = (wid & 1) << 6;     // code half (0/64)
    const int q  = lane >> 2;          // 0..7
    const int tg = lane & 3;           // 0..3
    const int r0 = mb + q, r1 = r0 + 8, r2 = r0 + 16, r3 = r0 + 24;

    // Hoist all A fragments (invariant across code tiles): 4 ks x 8 regs.
    unsigned Af[4][8];
#pragma unroll
    for (int ks = 0; ks < 4; ks++) {
        int p = ks * 8 + tg;
        Af[ks][0] = szb[(p    ) * LPAD + mb + q];
        Af[ks][1] = szb[(p    ) * LPAD + mb + q + 8];
        Af[ks][2] = szb[(p + 4) * LPAD + mb + q];
        Af[ks][3] = szb[(p + 4) * LPAD + mb + q + 8];
        Af[ks][4] = szb[(p    ) * LPAD + mb + q + 16];
        Af[ks][5] = szb[(p    ) * LPAD + mb + q + 24];
        Af[ks][6] = szb[(p + 4) * LPAD + mb + q + 16];
        Af[ks][7] = szb[(p + 4) * LPAD + mb + q + 24];
    }

    for (int ct = 0; ct < 8; ct++) {
        __syncthreads();   // scb/sen2t safe to overwrite
        // Load code tile: emb[ct*128+c][l] -> scb[l/2][c] (bf16x2 k-pairs)
        {
            int c = tid & 127, half = tid >> 7;
            const float4* src =
                (const float4*)(emb + ((size_t)(ct * 128 + c)) * LD + half * 32);
#pragma unroll
            for (int j = 0; j < 8; j++) {
                float4 v = src[j];
                int l2 = half * 16 + j * 2;
                scb[(l2    ) * LPAD + c] = pack_bf2(v.x, v.y);
                scb[(l2 + 1) * LPAD + c] = pack_bf2(v.z, v.w);
            }
            if (tid < 128) sen2t[tid] = g_en2[ct * 128 + tid];
        }
        __syncthreads();

        // Two ns-groups of 4: acc live range = 32 regs per group.
#pragma unroll
        for (int g = 0; g < 2; g++) {
            float acc[4][8];
#pragma unroll
            for (int ns = 0; ns < 4; ns++)
#pragma unroll
                for (int j = 0; j < 8; j++) acc[ns][j] = 0.0f;

#pragma unroll
            for (int ks = 0; ks < 4; ks++) {
                int p = ks * 8 + tg;
#pragma unroll
                for (int ns = 0; ns < 4; ns++) {
                    int cb = nh + (g * 4 + ns) * 8;
                    unsigned b0 = scb[(p    ) * LPAD + cb + q];
                    unsigned b1 = scb[(p + 4) * LPAD + cb + q];
                    MMA_BF16(acc[ns][0], acc[ns][1], acc[ns][2], acc[ns][3],
                             Af[ks][0], Af[ks][1], Af[ks][2], Af[ks][3], b0, b1);
                    MMA_BF16(acc[ns][4], acc[ns][5], acc[ns][6], acc[ns][7],
                             Af[ks][4], Af[ks][5], Af[ks][6], Af[ks][7], b0, b1);
                }
            }

            // Phase a: s~ = en2 - 2 m~, per-row min via smem atomicMin
            float m0 = __int_as_float(0x7f800000), m1 = m0, m2 = m0, m3 = m0;
#pragma unroll
            for (int ns = 0; ns < 4; ns++) {
                int cl = nh + (g * 4 + ns) * 8 + 2 * tg;
                float e0 = sen2t[cl], e1 = sen2t[cl + 1];
                acc[ns][0] = e0 - 2.0f * acc[ns][0];
                acc[ns][1] = e1 - 2.0f * acc[ns][1];
                acc[ns][2] = e0 - 2.0f * acc[ns][2];
                acc[ns][3] = e1 - 2.0f * acc[ns][3];
                acc[ns][4] = e0 - 2.0f * acc[ns][4];
                acc[ns][5] = e1 - 2.0f * acc[ns][5];
                acc[ns][6] = e0 - 2.0f * acc[ns][6];
                acc[ns][7] = e1 - 2.0f * acc[ns][7];
                m0 = fminf(m0, fminf(acc[ns][0], acc[ns][1]));
                m1 = fminf(m1, fminf(acc[ns][2], acc[ns][3]));
                m2 = fminf(m2, fminf(acc[ns][4], acc[ns][5]));
                m3 = fminf(m3, fminf(acc[ns][6], acc[ns][7]));
            }
            atomicMin(&sminkey[r0], fkey(m0));
            atomicMin(&sminkey[r1], fkey(m1));
            atomicMin(&sminkey[r2], fkey(m2));
            atomicMin(&sminkey[r3], fkey(m3));
            __syncthreads();

            // Phase b: collect candidates vs running min. Running min >= final
            // min, so threshold >= final_min + TAU -> over-collects only (safe).
            float t0 = funkey(sminkey[r0]) + TAU;
            float t1 = funkey(sminkey[r1]) + TAU;
            float t2 = funkey(sminkey[r2]) + TAU;
            float t3 = funkey(sminkey[r3]) + TAU;
#pragma unroll
            for (int ns = 0; ns < 4; ns++) {
                int k0 = ct * 128 + nh + (g * 4 + ns) * 8 + 2 * tg;
#pragma unroll
                for (int j = 0; j < 8; j++) {
                    int   row = (j < 2) ? r0 : (j < 4) ? r1 : (j < 6) ? r2 : r3;
                    float th  = (j < 2) ? t0 : (j < 4) ? t1 : (j < 6) ? t2 : t3;
                    if (acc[ns][j] <= th) {
                        int c = atomicAdd(&ccnt[row], 1);
                        if (c < CAND) cand[row * CAND + c] = k0 + (j & 1);
                    }
                }
            }
        }
    }
    __syncthreads();

    // Exact phase: one thread per row replays bit-exact reference arithmetic.
    if (tid < 128) {
        int r = tid;
        float a = 0.0f;
#pragma unroll
        for (int l = 0; l < LD; l++) {
            float v = szf[l * LPAD + r];
            a = __fadd_rn(a, __fmul_rn(v, v));
        }
        float best = __int_as_float(0x7f800000);
        int   bi   = 0;
        int   cnt  = ccnt[r];
        if (cnt <= CAND) {
            for (int j = 0; j < cnt; j++) {
                int k = cand[r * CAND + j];
                const float* e = emb + (size_t)k * LD;
                float m = 0.0f;
#pragma unroll
                for (int l = 0; l < LD; l++)
                    m = __fmaf_rn(szf[l * LPAD + r], __ldg(e + l), m);
                float d = __fadd_rn(__fadd_rn(a, __ldg(&g_en2[k])),
                                    __fmul_rn(-2.0f, m));
                if (d < best || (d == best && k < bi)) { best = d; bi = k; }
            }
        } else {  // overflow fallback: exact full scan (never expected)
            for (int k = 0; k < KCODES; k++) {
                const float* e = emb + (size_t)k * LD;
                float m = 0.0f;
#pragma unroll
                for (int l = 0; l < LD; l++)
                    m = __fmaf_rn(szf[l * LPAD + r], __ldg(e + l), m);
                float d = __fadd_rn(__fadd_rn(a, __ldg(&g_en2[k])),
                                    __fmul_rn(-2.0f, m));
                if (d < best) { best = d; bi = k; }
            }
        }
        int n = rowbase + r;
        g_idx[n]   = bi;
        out_idx[n] = (float)bi;
    }
}

// ---------------------------------------------------------------------------
// K3: gather z_q (float4), z_q_st = ze + (z_q - ze) in reference op order,
// block-reduce fl32((z_q-ze)^2) in double, one atomicAdd per block.
// ---------------------------------------------------------------------------
__global__ void __launch_bounds__(256)
gather_kernel(const float* __restrict__ ze, const float* __restrict__ emb,
              float* __restrict__ out) {
    __shared__ double swarp[8];
    int i   = (blockIdx.x * 256 + threadIdx.x) * 4;
    int b   = i >> 18;
    int rem = i & 262143;
    int l   = rem >> 12;
    int hw  = rem & 4095;
    int n   = (b << 12) | hw;

    int4   ki  = *(const int4*)(g_idx + n);
    float4 ze4 = *(const float4*)(ze + i);
    float t0 = __fadd_rn(emb[ki.x * LD + l], -ze4.x);
    float t1 = __fadd_rn(emb[ki.y * LD + l], -ze4.y);
    float t2 = __fadd_rn(emb[ki.z * LD + l], -ze4.z);
    float t3 = __fadd_rn(emb[ki.w * LD + l], -ze4.w);
    float4 o4;
    o4.x = __fadd_rn(ze4.x, t0);
    o4.y = __fadd_rn(ze4.y, t1);
    o4.z = __fadd_rn(ze4.z, t2);
    o4.w = __fadd_rn(ze4.w, t3);
    *(float4*)(out + i) = o4;

    double s = (double)__fmul_rn(t0, t0) + (double)__fmul_rn(t1, t1)
             + (double)__fmul_rn(t2, t2) + (double)__fmul_rn(t3, t3);
#pragma unroll
    for (int o = 16; o > 0; o >>= 1)
        s += __shfl_down_sync(0xffffffffu, s, o);
    int w = threadIdx.x >> 5, lid = threadIdx.x & 31;
    if (lid == 0) swarp[w] = s;
    __syncthreads();
    if (w == 0) {
        double v = (lid < 8) ? swarp[lid] : 0.0;
#pragma unroll
        for (int o = 4; o > 0; o >>= 1)
            v += __shfl_down_sync(0xffffffffu, v, o);
        if (lid == 0) atomicAdd(&g_loss, v);
    }
}

__global__ void loss_kernel(float* __restrict__ out) {
    out[ELEMS] = (float)(g_loss / (double)ELEMS * 1.25);
}

// ---------------------------------------------------------------------------
// Launch. Outputs: [z_q_st (4194304)] [loss (1)] [idx (65536)]
// ---------------------------------------------------------------------------
#define SMEM_SCREEN (64 * LPAD * 4 + 32 * LPAD * 4 + 32 * LPAD * 4 \
                     + 128 * 4 + 128 * 4 + 128 * 4 + 128 * CAND * 4)

extern "C" void kernel_launch(void* const* d_in, const int* in_sizes, int n_in,
                              void* d_out, int out_size) {
    const float* ze  = (const float*)d_in[0];
    const float* emb = (const float*)d_in[1];
    float* out     = (float*)d_out;
    float* out_idx = out + ELEMS + 1;

    cudaFuncSetAttribute(screen_kernel,
                         cudaFuncAttributeMaxDynamicSharedMemorySize,
                         SMEM_SCREEN);

    en2_kernel   <<<(KCODES + 255) / 256, 256>>>(emb);
    screen_kernel<<<NROWS / 128, 256, SMEM_SCREEN>>>(ze, emb, out_idx);
    gather_kernel<<<ELEMS / (256 * 4), 256>>>(ze, emb, out);
    loss_kernel  <<<1, 1>>>(out);
}